// round 16
// baseline (speedup 1.0000x reference)
#include <cuda_runtime.h>

#define MAX_N 65536

__device__ float g_p[MAX_N];    // x . w_rel  per node
__device__ float g_r[MAX_N];    // x . w_root per node
__device__ float g_agg[MAX_N];  // edge-aggregated p

// ---------------------------------------------------------------------------
// Kernel 1: per-node dual dot products. 8 lanes per node (4 nodes/warp),
// weights in shared memory. Epilogue zeroes g_agg for this node.
// ---------------------------------------------------------------------------
__global__ void k_scores(const float4* __restrict__ x4,
                         const float4* __restrict__ wrel4,
                         const float4* __restrict__ wroot4,
                         int N, int d4) {
    extern __shared__ float4 wsm[];
    int t = threadIdx.x;
    for (int c = t; c < 2 * d4; c += blockDim.x)
        wsm[c] = (c < d4) ? wrel4[c] : wroot4[c - d4];
    __syncthreads();
    const float4* wa = wsm;
    const float4* wb = wsm + d4;

    int warp = (blockIdx.x * blockDim.x + t) >> 5;
    int lane = t & 31;
    int sub  = lane >> 3;
    int l8   = lane & 7;
    int node = warp * 4 + sub;
    if (node >= N) return;

    const float4* xr = x4 + (size_t)node * d4;
    float sp = 0.f, sr = 0.f;
#pragma unroll 8
    for (int c = l8; c < d4; c += 8) {
        float4 xv = xr[c];
        float4 a  = wa[c];
        float4 b  = wb[c];
        sp += xv.x * a.x + xv.y * a.y + xv.z * a.z + xv.w * a.w;
        sr += xv.x * b.x + xv.y * b.y + xv.z * b.z + xv.w * b.w;
    }
#pragma unroll
    for (int o = 4; o; o >>= 1) {
        sp += __shfl_xor_sync(0xffffffffu, sp, o);
        sr += __shfl_xor_sync(0xffffffffu, sr, o);
    }
    if (l8 == 0) {
        g_p[node]   = sp;
        g_r[node]   = sr;
        g_agg[node] = 0.f;
    }
}

// ---------------------------------------------------------------------------
// Kernel 2: edge scatter-add across the WHOLE chip (192 L2 slices in
// parallel) instead of one SM's LSU per graph.
// ---------------------------------------------------------------------------
__global__ void k_edges(const int* __restrict__ src, const int* __restrict__ dst, int E) {
    int e = blockIdx.x * blockDim.x + threadIdx.x;
    if (e < E) atomicAdd(&g_agg[dst[e]], g_p[src[e]]);
}

// ---------------------------------------------------------------------------
// Kernel 3 (per-graph, 1024 threads): tanh scores from prefetched agg/r,
// histogram exact top-k (warp0 threshold finder, jax tie-break),
// deep-MLP float4 gather with atomic pooled, vectorized projection.
// NO edge phase, no p/agg staging -> 2 fewer barriers, no smem-ATOMS trap.
// ---------------------------------------------------------------------------
__global__ __launch_bounds__(1024, 1)
void k_pool(const float* __restrict__ x,
            const float* __restrict__ brel,
            const float* __restrict__ wproj,
            const float* __restrict__ bproj,
            float* __restrict__ out,
            int n, int k, int d, int odim, int nrep4) {
    extern __shared__ unsigned char sm[];
    float* svals   = (float*)sm;                                 // k
    int*   sidx    = (int*)(svals + k);                          // k
    unsigned* hist = (unsigned*)(sidx + k);                      // 256
    uint2* list    = (uint2*)(hist + 256);                       // n
    float* pooled  = (float*)(list + n);                         // d
    float* part    = pooled + d;                                 // nrepP * odim
    int*   ctrl    = (int*)(part + (1024 / (odim >> 2)) * odim); // cnt, m, tb, krem

    const int g    = blockIdx.x;
    const int t    = threadIdx.x;
    const int base = g * n;
    const int nt   = blockDim.x;
    const int d4   = d >> 2;
    const float inv_k = 1.0f / (float)k;

    // ---- prefetch this thread's score inputs (independent LDGs) ----
    const float br   = brel[0];
    const float areg = (t < n) ? g_agg[base + t] : 0.f;
    const float rreg = (t < n) ? g_r[base + t]   : 0.f;

    if (t < 4) ctrl[t] = 0;
    for (int b = t; b < 256; b += nt) hist[b] = 0;
    for (int i = t; i < d; i += nt) pooled[i] = 0.f;
    __syncthreads();

    // ---- tanh score -> monotone u32 bits (register) + bucket histogram ----
    unsigned myu = 0;
    if (t < n) {
        float s = tanhf(areg + br + rreg);
        unsigned u = __float_as_uint(s);
        myu = (u & 0x80000000u) ? ~u : (u | 0x80000000u);
        atomicAdd(&hist[myu >> 24], 1u);
    }
    __syncthreads();

    // ---- warp 0: threshold bucket via shuffle suffix scan (8 buckets/lane) --
    if (t < 32) {
        unsigned lane = t;
        unsigned h[8];
        unsigned local = 0;
#pragma unroll
        for (int j = 0; j < 8; j++) { h[j] = hist[lane * 8 + j]; local += h[j]; }
        unsigned sfx = local;
#pragma unroll
        for (int off = 1; off < 32; off <<= 1) {
            unsigned v = __shfl_down_sync(0xffffffffu, sfx, off);
            if (lane + off < 32) sfx += v;
        }
        unsigned nxt = __shfl_down_sync(0xffffffffu, sfx, 1);
        if (lane == 31) nxt = 0;
        unsigned running = nxt;                    // elems in buckets > lane*8+7
#pragma unroll
        for (int j = 7; j >= 0; j--) {
            unsigned incl = running + h[j];
            if (running < (unsigned)k && (unsigned)k <= incl) {
                ctrl[2] = (int)(lane * 8 + j);     // threshold bucket
                ctrl[3] = k - (int)running;        // take this many from it
            }
            running = incl;
        }
    }
    __syncthreads();

    const int tb   = ctrl[2];
    const int krem = ctrl[3];

    // ---- emit: clear winners (scaled by 1/k); threshold bucket -> list ----
    if (t < n) {
        int b = (int)(myu >> 24);
        if (b > tb) {
            int pos = atomicAdd(&ctrl[0], 1);
            unsigned fu = (myu & 0x80000000u) ? (myu & 0x7fffffffu) : ~myu;
            svals[pos] = __uint_as_float(fu) * inv_k;
            sidx[pos]  = t;
        } else if (b == tb) {
            int pos = atomicAdd(&ctrl[1], 1);
            list[pos] = make_uint2(myu, (unsigned)t);
        }
    }
    __syncthreads();

    // ---- fine rank within threshold bucket (smaller index wins ties) ----
    {
        const int m = ctrl[1];
        if (t < m) {
            uint2 me = list[t];
            int r = 0;
            for (int l = 0; l < m; l++) {
                uint2 o = list[l];
                r += (o.x > me.x) || (o.x == me.x && o.y < me.y);
            }
            if (r < krem) {
                int pos = atomicAdd(&ctrl[0], 1);
                unsigned fu = (me.x & 0x80000000u) ? (me.x & 0x7fffffffu) : ~me.x;
                svals[pos] = __uint_as_float(fu) * inv_k;
                sidx[pos]  = (int)me.y;
            }
        }
    }
    __syncthreads();

    // ---- gather: float4, 8 loads in flight, atomic-accumulate into pooled --
    {
        const int col4 = t % d4;
        const int rep  = t / d4;
        const int per  = (k + nrep4 - 1) / nrep4;
        const int j0   = rep * per;
        const int j1   = min(j0 + per, k);
        const float4* x4 = (const float4*)x;
        float4 a0 = {0,0,0,0}, a1 = {0,0,0,0}, a2 = {0,0,0,0}, a3 = {0,0,0,0};
        int j = j0;
        for (; j + 8 <= j1; j += 8) {
            float v[8]; int r[8];
#pragma unroll
            for (int u = 0; u < 8; u++) { v[u] = svals[j + u]; r[u] = sidx[j + u]; }
            float4 q[8];
#pragma unroll
            for (int u = 0; u < 8; u++)
                q[u] = x4[(size_t)(base + r[u]) * d4 + col4];
            a0.x += v[0]*q[0].x + v[4]*q[4].x; a0.y += v[0]*q[0].y + v[4]*q[4].y;
            a0.z += v[0]*q[0].z + v[4]*q[4].z; a0.w += v[0]*q[0].w + v[4]*q[4].w;
            a1.x += v[1]*q[1].x + v[5]*q[5].x; a1.y += v[1]*q[1].y + v[5]*q[5].y;
            a1.z += v[1]*q[1].z + v[5]*q[5].z; a1.w += v[1]*q[1].w + v[5]*q[5].w;
            a2.x += v[2]*q[2].x + v[6]*q[6].x; a2.y += v[2]*q[2].y + v[6]*q[6].y;
            a2.z += v[2]*q[2].z + v[6]*q[6].z; a2.w += v[2]*q[2].w + v[6]*q[6].w;
            a3.x += v[3]*q[3].x + v[7]*q[7].x; a3.y += v[3]*q[3].y + v[7]*q[7].y;
            a3.z += v[3]*q[3].z + v[7]*q[7].z; a3.w += v[3]*q[3].w + v[7]*q[7].w;
        }
        for (; j < j1; j++) {
            float v = svals[j];
            float4 q = x4[(size_t)(base + sidx[j]) * d4 + col4];
            a0.x += v*q.x; a0.y += v*q.y; a0.z += v*q.z; a0.w += v*q.w;
        }
        atomicAdd(&pooled[col4 * 4 + 0], a0.x + a1.x + a2.x + a3.x);
        atomicAdd(&pooled[col4 * 4 + 1], a0.y + a1.y + a2.y + a3.y);
        atomicAdd(&pooled[col4 * 4 + 2], a0.z + a1.z + a2.z + a3.z);
        atomicAdd(&pooled[col4 * 4 + 3], a0.w + a1.w + a2.w + a3.w);
    }

    // projection-weight prefetch across the barrier (independent of pooled)
    const int od4   = odim >> 2;
    const int o4    = t % od4;
    const int prep  = t / od4;
    const int nrepP = nt / od4;            // 16
    const int chunk = d / nrepP;           // 16
    const int d0    = prep * chunk;
    const float4* w4 = (const float4*)wproj;
    float4 wpre[4];
#pragma unroll
    for (int u = 0; u < 4; u++)
        wpre[u] = w4[(size_t)(d0 + u) * od4 + o4];
    __syncthreads();

    // ---- vectorized projection (first 4 weights already in registers) ----
    {
        float4 acc = {0, 0, 0, 0};
#pragma unroll
        for (int u = 0; u < 4; u++) {
            float pv = pooled[d0 + u];
            acc.x += pv * wpre[u].x; acc.y += pv * wpre[u].y;
            acc.z += pv * wpre[u].z; acc.w += pv * wpre[u].w;
        }
#pragma unroll 4
        for (int dd = d0 + 4; dd < d0 + chunk; dd++) {
            float pv = pooled[dd];
            float4 w = w4[(size_t)dd * od4 + o4];
            acc.x += pv * w.x; acc.y += pv * w.y;
            acc.z += pv * w.z; acc.w += pv * w.w;
        }
        ((float4*)part)[prep * od4 + o4] = acc;
    }
    __syncthreads();

    if (t < od4) {
        float4 acc = ((float4*)part)[t];
        for (int rr = 1; rr < nrepP; rr++) {
            float4 q = ((float4*)part)[rr * od4 + t];
            acc.x += q.x; acc.y += q.y; acc.z += q.z; acc.w += q.w;
        }
        float4 b = ((const float4*)bproj)[t];
        float4 o;
        o.x = acc.x + b.x; o.y = acc.y + b.y;
        o.z = acc.z + b.z; o.w = acc.w + b.w;
        ((float4*)out)[(size_t)g * od4 + t] = o;
    }
}

// ---------------------------------------------------------------------------
// Inputs: x, edge_index, batch, num_graphs, w_rel, b_rel, w_root, w_proj, b_proj.
// Output: [B, out_dim] float32.
// ---------------------------------------------------------------------------
extern "C" void kernel_launch(void* const* d_in, const int* in_sizes, int n_in,
                              void* d_out, int out_size) {
    const float* x     = (const float*)d_in[0];
    const int*   ei    = (const int*)d_in[1];
    const float* wrel  = (const float*)d_in[4];
    const float* brel  = (const float*)d_in[5];
    const float* wroot = (const float*)d_in[6];
    const float* wproj = (const float*)d_in[7];
    const float* bproj = (const float*)d_in[8];
    float* out = (float*)d_out;

    const int odim = in_sizes[8];
    const int d    = in_sizes[7] / odim;
    const int N    = in_sizes[0] / d;
    const int E    = in_sizes[1] / 2;
    const int B    = out_size / odim;
    const int n    = N / B;
    const int k    = (n + 1) / 2;     // ceil(0.5 * n), RATIO = 0.5
    const int d4   = d / 4;
    const int nrep4 = 1024 / d4;      // 16 for d=256

    // K1: scores (+ zero g_agg)
    int warps = (N + 3) / 4;
    size_t smem1 = (size_t)(2 * d4) * sizeof(float4);
    k_scores<<<(warps * 32 + 255) / 256, 256, smem1>>>(
        (const float4*)x, (const float4*)wrel, (const float4*)wroot, N, d4);

    // K2: chip-wide edge scatter (src row = ei[0:E), dst row = ei[E:2E))
    k_edges<<<(E + 255) / 256, 256>>>(ei, ei + E, E);

    // K3: pool
    const int nrepP = 1024 / (odim / 4);
    size_t smem2 = (size_t)k * 8                 // svals + sidx
                 + 256 * 4                       // hist
                 + (size_t)n * 8                 // fine list
                 + (size_t)d * 4                 // pooled
                 + (size_t)nrepP * odim * 4      // projection partials
                 + 32;                           // ctrl + pad
    k_pool<<<B, 1024, smem2>>>(x, brel, wproj, bproj, out, n, k, d, odim, nrep4);
}

// round 17
// speedup vs baseline: 1.6334x; 1.6334x over previous
#include <cuda_runtime.h>

#define MAX_N 65536
#define EPT 8   // edge pairs prefetched per select-thread (Eg=4096 / 512)

__device__ float g_p[MAX_N];    // x . w_rel  per node
__device__ float g_r[MAX_N];    // x . w_root per node

// ---------------------------------------------------------------------------
// Kernel 1: per-node dual dot products. 8 lanes per node (4 nodes/warp),
// weights in shared memory. (Proven ~6.3us steady; x stays L2-resident.)
// ---------------------------------------------------------------------------
__global__ void k_scores(const float4* __restrict__ x4,
                         const float4* __restrict__ wrel4,
                         const float4* __restrict__ wroot4,
                         int N, int d4) {
    extern __shared__ float4 wsm[];
    int t = threadIdx.x;
    for (int c = t; c < 2 * d4; c += blockDim.x)
        wsm[c] = (c < d4) ? wrel4[c] : wroot4[c - d4];
    __syncthreads();
    const float4* wa = wsm;
    const float4* wb = wsm + d4;

    int warp = (blockIdx.x * blockDim.x + t) >> 5;
    int lane = t & 31;
    int sub  = lane >> 3;
    int l8   = lane & 7;
    int node = warp * 4 + sub;
    if (node >= N) return;

    const float4* xr = x4 + (size_t)node * d4;
    float sp = 0.f, sr = 0.f;
#pragma unroll 8
    for (int c = l8; c < d4; c += 8) {
        float4 xv = xr[c];
        float4 a  = wa[c];
        float4 b  = wb[c];
        sp += xv.x * a.x + xv.y * a.y + xv.z * a.z + xv.w * a.w;
        sr += xv.x * b.x + xv.y * b.y + xv.z * b.z + xv.w * b.w;
    }
#pragma unroll
    for (int o = 4; o; o >>= 1) {
        sp += __shfl_xor_sync(0xffffffffu, sp, o);
        sr += __shfl_xor_sync(0xffffffffu, sr, o);
    }
    if (l8 == 0) {
        g_p[node] = sp;
        g_r[node] = sr;
    }
}

// ---------------------------------------------------------------------------
// Kernel 2 (per-graph, 1024 threads, warp-specialized):
//   warps 0-15 : selection pipeline (edges -> tanh -> histogram top-k),
//                synchronized with named barrier (bar.sync 1, 512)
//   warps 16-31: concurrently stage wproj rows [0, dstage) into smem
//   join -> float4 gather (all warps) -> projection (smem + global tail).
// ---------------------------------------------------------------------------
__global__ __launch_bounds__(1024, 1)
void k_pool(const float* __restrict__ x,
            const int* __restrict__ ei,
            const float* __restrict__ brel,
            const float* __restrict__ wproj,
            const float* __restrict__ bproj,
            float* __restrict__ out,
            int n, int k, int d, int odim, int E, int Eg, int nrep4, int dstage) {
    extern __shared__ unsigned char sm[];
    const int od4 = odim >> 2;
    float4* wsm    = (float4*)sm;                                // dstage * od4
    float* p_s     = (float*)(wsm + (size_t)dstage * od4);       // n
    float* agg_s   = p_s + n;                                    // n
    float* svals   = agg_s + n;                                  // k
    int*   sidx    = (int*)(svals + k);                          // k
    unsigned* hist = (unsigned*)(sidx + k);                      // 256
    uint2* list    = (uint2*)(hist + 256);                       // n
    float* part    = (float*)(list + n);                         // nrep4 * d
    float* pooled  = part + nrep4 * d;                           // d
    int*   ctrl    = (int*)(pooled + d);                         // cnt, m, tb, krem

    const int g    = blockIdx.x;
    const int t    = threadIdx.x;
    const int base = g * n;
    const int nt   = blockDim.x;
    const int d4   = d >> 2;

    if (t < 512) {
        // ================= SELECT GROUP (warps 0-15) =================
        int es[EPT], ed[EPT];
        const int eb = g * Eg;
#pragma unroll
        for (int q = 0; q < EPT; q++) {
            int e = t + q * 512;
            if (e < Eg) {
                es[q] = ei[eb + e] - base;
                ed[q] = ei[E + eb + e] - base;
            } else { es[q] = 0; ed[q] = -1; }
        }
        const float br   = brel[0];
        const float rreg = (t < n) ? g_r[base + t] : 0.f;

        if (t < 4) ctrl[t] = 0;
        for (int b = t; b < 256; b += 512) hist[b] = 0;
        for (int i = t; i < n; i += 512) {
            p_s[i]   = g_p[base + i];
            agg_s[i] = 0.f;
        }
        asm volatile("bar.sync 1, 512;" ::: "memory");

        // edge aggregation from registers (LDS + ATOMS only)
#pragma unroll
        for (int q = 0; q < EPT; q++)
            if (ed[q] >= 0) atomicAdd(&agg_s[ed[q]], p_s[es[q]]);
        for (int e = EPT * 512 + t; e < Eg; e += 512)
            atomicAdd(&agg_s[ei[E + eb + e] - base], p_s[ei[eb + e] - base]);
        asm volatile("bar.sync 1, 512;" ::: "memory");

        // tanh score -> monotone u32 bits + bucket histogram
        unsigned myu = 0;
        if (t < n) {
            float s = tanhf(agg_s[t] + br + rreg);
            unsigned u = __float_as_uint(s);
            myu = (u & 0x80000000u) ? ~u : (u | 0x80000000u);
            atomicAdd(&hist[myu >> 24], 1u);
        }
        asm volatile("bar.sync 1, 512;" ::: "memory");

        // warp 0: threshold bucket via shuffle suffix scan (8 buckets/lane)
        if (t < 32) {
            unsigned lane = t;
            unsigned h[8];
            unsigned local = 0;
#pragma unroll
            for (int j = 0; j < 8; j++) { h[j] = hist[lane * 8 + j]; local += h[j]; }
            unsigned sfx = local;
#pragma unroll
            for (int off = 1; off < 32; off <<= 1) {
                unsigned v = __shfl_down_sync(0xffffffffu, sfx, off);
                if (lane + off < 32) sfx += v;
            }
            unsigned nxt = __shfl_down_sync(0xffffffffu, sfx, 1);
            if (lane == 31) nxt = 0;
            unsigned running = nxt;               // elems in buckets > lane*8+7
#pragma unroll
            for (int j = 7; j >= 0; j--) {
                unsigned incl = running + h[j];
                if (running < (unsigned)k && (unsigned)k <= incl) {
                    ctrl[2] = (int)(lane * 8 + j);
                    ctrl[3] = k - (int)running;
                }
                running = incl;
            }
        }
        asm volatile("bar.sync 1, 512;" ::: "memory");

        const int tb   = ctrl[2];
        const int krem = ctrl[3];

        // emit: clear winners; threshold bucket -> fine list
        if (t < n) {
            int b = (int)(myu >> 24);
            if (b > tb) {
                int pos = atomicAdd(&ctrl[0], 1);
                unsigned fu = (myu & 0x80000000u) ? (myu & 0x7fffffffu) : ~myu;
                svals[pos] = __uint_as_float(fu);
                sidx[pos]  = t;
            } else if (b == tb) {
                int pos = atomicAdd(&ctrl[1], 1);
                list[pos] = make_uint2(myu, (unsigned)t);
            }
        }
        asm volatile("bar.sync 1, 512;" ::: "memory");

        // fine rank within threshold bucket (smaller index wins ties)
        {
            const int m = ctrl[1];
            if (t < m) {
                uint2 me = list[t];
                int r = 0;
                for (int l = 0; l < m; l++) {
                    uint2 o = list[l];
                    r += (o.x > me.x) || (o.x == me.x && o.y < me.y);
                }
                if (r < krem) {
                    int pos = atomicAdd(&ctrl[0], 1);
                    unsigned fu = (me.x & 0x80000000u) ? (me.x & 0x7fffffffu) : ~me.x;
                    svals[pos] = __uint_as_float(fu);
                    sidx[pos]  = (int)me.y;
                }
            }
        }
    } else {
        // ================= LOADER GROUP (warps 16-31) =================
        // stage wproj rows [0, dstage) into smem while selection runs
        const float4* w4 = (const float4*)wproj;
        const int tot = dstage * od4;
#pragma unroll 8
        for (int c = t - 512; c < tot; c += 512)
            wsm[c] = w4[c];
    }
    __syncthreads();

    // ---- weighted mean: float4 gather, 8 loads in flight per thread ----
    {
        const int col4 = t % d4;
        const int rep  = t / d4;
        const int per  = (k + nrep4 - 1) / nrep4;
        const int j0   = rep * per;
        const int j1   = min(j0 + per, k);
        const float4* x4 = (const float4*)x;
        float4 a0 = {0,0,0,0}, a1 = {0,0,0,0}, a2 = {0,0,0,0}, a3 = {0,0,0,0};
        int j = j0;
        for (; j + 8 <= j1; j += 8) {
            float v[8]; int r[8];
#pragma unroll
            for (int u = 0; u < 8; u++) { v[u] = svals[j + u]; r[u] = sidx[j + u]; }
            float4 q[8];
#pragma unroll
            for (int u = 0; u < 8; u++)
                q[u] = x4[(size_t)(base + r[u]) * d4 + col4];
            a0.x += v[0]*q[0].x + v[4]*q[4].x; a0.y += v[0]*q[0].y + v[4]*q[4].y;
            a0.z += v[0]*q[0].z + v[4]*q[4].z; a0.w += v[0]*q[0].w + v[4]*q[4].w;
            a1.x += v[1]*q[1].x + v[5]*q[5].x; a1.y += v[1]*q[1].y + v[5]*q[5].y;
            a1.z += v[1]*q[1].z + v[5]*q[5].z; a1.w += v[1]*q[1].w + v[5]*q[5].w;
            a2.x += v[2]*q[2].x + v[6]*q[6].x; a2.y += v[2]*q[2].y + v[6]*q[6].y;
            a2.z += v[2]*q[2].z + v[6]*q[6].z; a2.w += v[2]*q[2].w + v[6]*q[6].w;
            a3.x += v[3]*q[3].x + v[7]*q[7].x; a3.y += v[3]*q[3].y + v[7]*q[7].y;
            a3.z += v[3]*q[3].z + v[7]*q[7].z; a3.w += v[3]*q[3].w + v[7]*q[7].w;
        }
        for (; j < j1; j++) {
            float v = svals[j];
            float4 q = x4[(size_t)(base + sidx[j]) * d4 + col4];
            a0.x += v*q.x; a0.y += v*q.y; a0.z += v*q.z; a0.w += v*q.w;
        }
        float4 s;
        s.x = a0.x + a1.x + a2.x + a3.x;
        s.y = a0.y + a1.y + a2.y + a3.y;
        s.z = a0.z + a1.z + a2.z + a3.z;
        s.w = a0.w + a1.w + a2.w + a3.w;
        ((float4*)part)[rep * d4 + col4] = s;
    }
    __syncthreads();

    // pooled reduce; prefetch global-tail projection weights across barrier
    const int o4    = t % od4;
    const int prep  = t / od4;
    const int nrepP = nt / od4;            // 16
    const int chunk = d / nrepP;           // 16
    const int d0    = prep * chunk;
    const float4* w4 = (const float4*)wproj;
    float4 wpre[4];
    if (d0 >= dstage) {
#pragma unroll
        for (int u = 0; u < 4; u++)        // independent of pooled: issue early
            wpre[u] = w4[(size_t)(d0 + u) * od4 + o4];
    }

    if (t < d) {
        float s = 0.f;
        for (int rr = 0; rr < nrep4; rr++) s += part[rr * d + t];
        pooled[t] = s / (float)k;
    }
    __syncthreads();

    // ---- projection: smem weights for staged rows, global for the tail ----
    {
        float4 acc = {0, 0, 0, 0};
        if (d0 < dstage) {
#pragma unroll 4
            for (int dd = d0; dd < d0 + chunk; dd++) {
                float pv = pooled[dd];
                float4 w = wsm[dd * od4 + o4];
                acc.x += pv * w.x; acc.y += pv * w.y;
                acc.z += pv * w.z; acc.w += pv * w.w;
            }
        } else {
#pragma unroll
            for (int u = 0; u < 4; u++) {
                float pv = pooled[d0 + u];
                acc.x += pv * wpre[u].x; acc.y += pv * wpre[u].y;
                acc.z += pv * wpre[u].z; acc.w += pv * wpre[u].w;
            }
#pragma unroll 4
            for (int dd = d0 + 4; dd < d0 + chunk; dd++) {
                float pv = pooled[dd];
                float4 w = w4[(size_t)dd * od4 + o4];
                acc.x += pv * w.x; acc.y += pv * w.y;
                acc.z += pv * w.z; acc.w += pv * w.w;
            }
        }
        ((float4*)part)[prep * od4 + o4] = acc;
    }
    __syncthreads();

    if (t < od4) {
        float4 acc = ((float4*)part)[t];
        for (int rr = 1; rr < nrepP; rr++) {
            float4 q = ((float4*)part)[rr * od4 + t];
            acc.x += q.x; acc.y += q.y; acc.z += q.z; acc.w += q.w;
        }
        float4 b = ((const float4*)bproj)[t];
        float4 o;
        o.x = acc.x + b.x; o.y = acc.y + b.y;
        o.z = acc.z + b.z; o.w = acc.w + b.w;
        ((float4*)out)[(size_t)g * od4 + t] = o;
    }
}

// ---------------------------------------------------------------------------
// Inputs: x, edge_index, batch, num_graphs, w_rel, b_rel, w_root, w_proj, b_proj.
// Output: [B, out_dim] float32.
// ---------------------------------------------------------------------------
extern "C" void kernel_launch(void* const* d_in, const int* in_sizes, int n_in,
                              void* d_out, int out_size) {
    const float* x     = (const float*)d_in[0];
    const int*   ei    = (const int*)d_in[1];
    const float* wrel  = (const float*)d_in[4];
    const float* brel  = (const float*)d_in[5];
    const float* wroot = (const float*)d_in[6];
    const float* wproj = (const float*)d_in[7];
    const float* bproj = (const float*)d_in[8];
    float* out = (float*)d_out;

    const int odim = in_sizes[8];
    const int d    = in_sizes[7] / odim;
    const int N    = in_sizes[0] / d;
    const int E    = in_sizes[1] / 2;
    const int B    = out_size / odim;
    const int n    = N / B;
    const int k    = (n + 1) / 2;     // ceil(0.5 * n), RATIO = 0.5
    const int Eg   = E / B;
    const int d4   = d / 4;
    const int nrep4 = 1024 / d4;      // 16 for d=256
    const int dstage = (d * 3) / 4;   // 192 rows of wproj staged in smem

    // K1: scores
    int warps = (N + 3) / 4;
    size_t smem1 = (size_t)(2 * d4) * sizeof(float4);
    k_scores<<<(warps * 32 + 255) / 256, 256, smem1>>>(
        (const float4*)x, (const float4*)wrel, (const float4*)wroot, N, d4);

    // K2: pool (needs >48KB dynamic smem -> opt-in, idempotent each call)
    size_t smem2 = (size_t)dstage * odim * 4     // staged wproj rows
                 + (size_t)n * 8                 // p, agg
                 + (size_t)k * 8                 // svals + sidx
                 + 256 * 4                       // hist
                 + (size_t)n * 8                 // fine list
                 + (size_t)nrep4 * d * 4         // part
                 + (size_t)d * 4                 // pooled
                 + 32;                           // ctrl + pad
    cudaFuncSetAttribute(k_pool, cudaFuncAttributeMaxDynamicSharedMemorySize,
                         (int)smem2);
    k_pool<<<B, 1024, smem2>>>(x, ei, brel, wproj, bproj, out,
                               n, k, d, odim, E, Eg, nrep4, dstage);
}